// round 1
// baseline (speedup 1.0000x reference)
#include <cuda_runtime.h>

#define TB   128        // threads per block = batch elements per block
#define HD   10         // HDIM
#define MSZ  41         // M
#define RECF 48         // floats per packed s-record (12 float4)
#define MAXS 512        // upper bound on S (actual S = 419)

// Packed per-s record: [0..2]=E-row indices (pre-*2), [3]=pad,
// [4,5]=pbc_C re/im, [6,7]=pad, [8..47]=W1[o][i] complex (o-major)
__device__ float g_rec1[MAXS * RECF];
// Packed per-k record for W2: 40 floats = W2[o][i] complex
__device__ float g_rec2[MSZ * 40];

__global__ void prep_kernel(const float* __restrict__ pbc_C,
                            const float* __restrict__ W1,
                            const float* __restrict__ W2,
                            const int*   __restrict__ m_idx,
                            const int*   __restrict__ n_idx,
                            int S) {
    int tid = blockIdx.x * blockDim.x + threadIdx.x;
    const int c = MSZ / 2;
    if (tid < S && tid < MAXS) {
        int s = tid;
        float* r = g_rec1 + s * RECF;
        int m = m_idx[s], n = n_idx[s];
        r[0] = __int_as_float(2 * (c + m));
        r[1] = __int_as_float(2 * (c + m + n));
        r[2] = __int_as_float(2 * (c + n));
        r[3] = 0.f;
        r[4] = pbc_C[2 * s + 0];
        r[5] = pbc_C[2 * s + 1];
        r[6] = 0.f; r[7] = 0.f;
#pragma unroll
        for (int oi = 0; oi < 2 * HD; oi++) {
            r[8 + 2 * oi + 0] = W1[(oi * S + s) * 2 + 0];
            r[8 + 2 * oi + 1] = W1[(oi * S + s) * 2 + 1];
        }
    }
    if (tid < MSZ) {
        int k = tid;
#pragma unroll
        for (int oi = 0; oi < 2 * HD; oi++) {
            g_rec2[k * 40 + 2 * oi + 0] = W2[(oi * MSZ + k) * 2 + 0];
            g_rec2[k * 40 + 2 * oi + 1] = W2[(oi * MSZ + k) * 2 + 1];
        }
    }
}

__global__ __launch_bounds__(TB) void eqsonn_kernel(
    const float* __restrict__ x,
    const float* __restrict__ task,
    const float* __restrict__ b1,
    const float* __restrict__ b2,
    float* __restrict__ out,
    int S, int Btot) {
    // Esh[row][tid], row = 2*k + pol, each float2 = one complex E value.
    extern __shared__ float2 Esh[];
    const int t = threadIdx.x;
    const int b = blockIdx.x * TB + t;
    if (b >= Btot) return;

    // ---- Load E row for this batch element into shared (own column only) ----
    const float4* xr = (const float4*)(x + (size_t)b * (MSZ * 4));
#pragma unroll
    for (int j = 0; j < MSZ; j++) {
        float4 v = xr[j];
        Esh[(2 * j) * TB + t]     = make_float2(v.x, v.y);  // pol 0
        Esh[(2 * j + 1) * TB + t] = make_float2(v.z, v.w);  // pol 1
    }
    // No __syncthreads needed: each thread only touches its own column.

    // ---- conv2 accumulators: Bm[o][variant] ----
    float Br[HD][2], Bi[HD][2];
#pragma unroll
    for (int o = 0; o < HD; o++) { Br[o][0] = Br[o][1] = Bi[o][0] = Bi[o][1] = 0.f; }

    for (int k = 0; k < MSZ; k++) {
        float2 e0 = Esh[(2 * k) * TB + t];
        float2 e1 = Esh[(2 * k + 1) * TB + t];
        const float4* w = (const float4*)(g_rec2 + k * 40);
#pragma unroll
        for (int o = 0; o < HD; o++) {
            float4 q = w[o];  // W2[o][0].re/.im, W2[o][1].re/.im
            Br[o][0] += q.x * e0.x - q.y * e0.y + q.z * e1.x - q.w * e1.y;
            Bi[o][0] += q.x * e0.y + q.y * e0.x + q.z * e1.y + q.w * e1.x;
            Br[o][1] += q.x * e1.x - q.y * e1.y + q.z * e0.x - q.w * e0.y;
            Bi[o][1] += q.x * e1.y + q.y * e1.x + q.z * e0.y + q.w * e0.x;
        }
    }

    // ---- conv1 accumulators A[o][variant] + pbc feature dot ----
    float Ar[HD][2], Ai[HD][2];
#pragma unroll
    for (int o = 0; o < HD; o++) { Ar[o][0] = Ar[o][1] = Ai[o][0] = Ai[o][1] = 0.f; }
    float pr0 = 0.f, pi0 = 0.f, pr1 = 0.f, pi1 = 0.f;

    for (int s = 0; s < S; s++) {
        const float4* r = (const float4*)(g_rec1 + s * RECF);
        float4 h0 = r[0];
        float4 h1 = r[1];
        int k1 = __float_as_int(h0.x);
        int k2 = __float_as_int(h0.y);
        int k3 = __float_as_int(h0.z);
        float2 a0 = Esh[k1 * TB + t], a1 = Esh[(k1 + 1) * TB + t];
        float2 q0 = Esh[k2 * TB + t], q1 = Esh[(k2 + 1) * TB + t];
        float2 n0 = Esh[k3 * TB + t], n1 = Esh[(k3 + 1) * TB + t];
        // Asum = a0*conj(q0) + a1*conj(q1)   (pol-summed triplet kernel)
        float Asr = a0.x * q0.x + a0.y * q0.y + a1.x * q1.x + a1.y * q1.y;
        float Asi = a0.y * q0.x - a0.x * q0.y + a1.y * q1.x - a1.x * q1.y;
        // F_p = Asum * E[c+n, p]
        float F0r = Asr * n0.x - Asi * n0.y, F0i = Asr * n0.y + Asi * n0.x;
        float F1r = Asr * n1.x - Asi * n1.y, F1i = Asr * n1.y + Asi * n1.x;
        // pbc dot: F_p * C[s]
        pr0 += F0r * h1.x - F0i * h1.y;  pi0 += F0r * h1.y + F0i * h1.x;
        pr1 += F1r * h1.x - F1i * h1.y;  pi1 += F1r * h1.y + F1i * h1.x;
        const float4* w = r + 2;
#pragma unroll
        for (int o = 0; o < HD; o++) {
            float4 q = w[o];  // W1[o][0].re/.im, W1[o][1].re/.im
            Ar[o][0] += q.x * F0r - q.y * F0i + q.z * F1r - q.w * F1i;
            Ai[o][0] += q.x * F0i + q.y * F0r + q.z * F1i + q.w * F1r;
            Ar[o][1] += q.x * F1r - q.y * F1i + q.z * F0r - q.w * F0i;
            Ai[o][1] += q.x * F1i + q.y * F1r + q.z * F0i + q.w * F0r;
        }
    }

    // ---- epilogue ----
    float tsk = task[(size_t)b * 4];
    float P = exp10f(tsk * 0.1f) * 0.5f;   // 10^(dBm/10) / NMODES
    const float scl = 3.16227766016837939e-05f;  // 1e-4 / sqrt(10)
    float sc = scl * P * P;
    const int crow = 2 * (MSZ / 2);
    float2 Ec0 = Esh[crow * TB + t];
    float2 Ec1 = Esh[(crow + 1) * TB + t];

    float o0r, o0i, o1r, o1i;
    {   // variant 0
        float tr = 0.f, tim = 0.f;
#pragma unroll
        for (int o = 0; o < HD; o++) {
            float ar = Ar[o][0] + b1[2 * o], ai = Ai[o][0] + b1[2 * o + 1];
            float br = Br[o][0] + b2[2 * o], bi = Bi[o][0] + b2[2 * o + 1];
            float rr = 2.f * (ar * br + ai * bi);   // A*conj(B)+conj(A)*B is real
            tr  += rr * br;
            tim += rr * bi;
        }
        o0r = Ec0.x + P * pr0 + sc * tr;
        o0i = Ec0.y + P * pi0 + sc * tim;
    }
    {   // variant 1 (pol-flipped)
        float tr = 0.f, tim = 0.f;
#pragma unroll
        for (int o = 0; o < HD; o++) {
            float ar = Ar[o][1] + b1[2 * o], ai = Ai[o][1] + b1[2 * o + 1];
            float br = Br[o][1] + b2[2 * o], bi = Bi[o][1] + b2[2 * o + 1];
            float rr = 2.f * (ar * br + ai * bi);
            tr  += rr * br;
            tim += rr * bi;
        }
        o1r = Ec1.x + P * pr1 + sc * tr;
        o1i = Ec1.y + P * pi1 + sc * tim;
    }
    *(float4*)(out + (size_t)b * 4) = make_float4(o0r, o0i, o1r, o1i);
}

extern "C" void kernel_launch(void* const* d_in, const int* in_sizes, int n_in,
                              void* d_out, int out_size) {
    const float* x     = (const float*)d_in[0];
    const float* task  = (const float*)d_in[1];
    const float* pbc_C = (const float*)d_in[2];
    const float* W1    = (const float*)d_in[3];
    const float* b1    = (const float*)d_in[4];
    const float* W2    = (const float*)d_in[5];
    const float* b2    = (const float*)d_in[6];
    const int*   m_idx = (const int*)d_in[7];
    const int*   n_idx = (const int*)d_in[8];
    int S = in_sizes[7];          // number of triplets
    if (S > MAXS) S = MAXS;
    int B = out_size / 4;         // [B, 2, 2] floats

    size_t smem = (size_t)(2 * MSZ) * TB * sizeof(float2);  // 83968 B
    cudaFuncSetAttribute(eqsonn_kernel,
                         cudaFuncAttributeMaxDynamicSharedMemorySize, (int)smem);

    int pthreads = 128;
    int pblocks = (S + pthreads - 1) / pthreads;
    prep_kernel<<<pblocks, pthreads>>>(pbc_C, W1, W2, m_idx, n_idx, S);

    int blocks = (B + TB - 1) / TB;
    eqsonn_kernel<<<blocks, TB, smem>>>(x, task, b1, b2, (float*)d_out, S, B);
}

// round 2
// speedup vs baseline: 2.6981x; 2.6981x over previous
#include <cuda_runtime.h>

#define TB   128        // threads per block = batch elements per block
#define HD   10         // HDIM
#define MSZ  41         // M
#define MAXP 256        // max s-pairs (S<=512)
#define P2   21         // k-pairs for conv2 (ceil(41/2))

typedef unsigned long long u64;

// Packed pair-records built by prep kernel.
// rec1: per s-pair j (s=2j,2j+1), 96 floats:
//  [0..2]  idx_e (k1,k2,k3 as int bits, pre-*2), [3] pad
//  [4..6]  idx_o, [7] pad
//  [8,9]   C.re (e,o)   [10,11] C.im (e,o)
//  [12..15] pad
//  [16 + o*8 + i*4 + {0,1}] = W1[o][i].re (e,o); {2,3} = W1[o][i].im (e,o)
__device__ float g_rec1[MAXP * 96];
// rec2: per k-pair j, 80 floats: [o*8 + i*4 + {0,1}] = W2[o][i].re (e,o); {2,3}=im
__device__ float g_rec2[P2 * 80];

__device__ __forceinline__ u64 pk(float lo, float hi) {
    u64 r; asm("mov.b64 %0,{%1,%2};" : "=l"(r) : "f"(lo), "f"(hi)); return r;
}
__device__ __forceinline__ float2 upk(u64 v) {
    float2 f; asm("mov.b64 {%0,%1},%2;" : "=f"(f.x), "=f"(f.y) : "l"(v)); return f;
}
__device__ __forceinline__ void fma2(u64 &a, u64 x, u64 y) {
    asm("fma.rn.f32x2 %0,%1,%2,%0;" : "+l"(a) : "l"(x), "l"(y));
}
__device__ __forceinline__ u64 ng(u64 v) { return v ^ 0x8000000080000000ULL; }

__global__ void prep_kernel(const float* __restrict__ pbc_C,
                            const float* __restrict__ W1,
                            const float* __restrict__ W2,
                            const int*   __restrict__ m_idx,
                            const int*   __restrict__ n_idx,
                            int S) {
    int j = blockIdx.x * blockDim.x + threadIdx.x;
    int P1 = (S + 1) / 2;
    const int c = MSZ / 2;
    if (j < P1) {
        float* r = g_rec1 + j * 96;
        r[3] = 0.f; r[7] = 0.f;
        r[12] = r[13] = r[14] = r[15] = 0.f;
#pragma unroll
        for (int h = 0; h < 2; h++) {
            int s = 2 * j + h;
            bool v = (s < S);
            int m = v ? m_idx[s] : 0;
            int n = v ? n_idx[s] : 0;
            r[4 * h + 0] = __int_as_float(v ? 2 * (c + m) : 0);
            r[4 * h + 1] = __int_as_float(v ? 2 * (c + m + n) : 0);
            r[4 * h + 2] = __int_as_float(v ? 2 * (c + n) : 0);
            r[8 + h]  = v ? pbc_C[2 * s + 0] : 0.f;
            r[10 + h] = v ? pbc_C[2 * s + 1] : 0.f;
#pragma unroll
            for (int oi = 0; oi < 2 * HD; oi++) {
                int base = 16 + oi * 4;
                r[base + h]     = v ? W1[(oi * S + s) * 2 + 0] : 0.f;
                r[base + 2 + h] = v ? W1[(oi * S + s) * 2 + 1] : 0.f;
            }
        }
    }
    if (j < P2) {
        float* r = g_rec2 + j * 80;
#pragma unroll
        for (int h = 0; h < 2; h++) {
            int k = 2 * j + h;
            bool v = (k < MSZ);
#pragma unroll
            for (int oi = 0; oi < 2 * HD; oi++) {
                int base = oi * 4;
                r[base + h]     = v ? W2[(oi * MSZ + k) * 2 + 0] : 0.f;
                r[base + 2 + h] = v ? W2[(oi * MSZ + k) * 2 + 1] : 0.f;
            }
        }
    }
}

__global__ __launch_bounds__(TB) void eqsonn_kernel(
    const float* __restrict__ x,
    const float* __restrict__ task,
    const float* __restrict__ b1g,
    const float* __restrict__ b2g,
    float* __restrict__ out,
    int S, int Btot) {
    extern __shared__ float sm[];
    // Esh: 84 rows (82 used + 2 zero-pad for conv2 k=41 pad reads)
    float2* Esh = (float2*)sm;                 // 84*TB float2
    float*  R1  = sm + 84 * TB * 2;            // P1*96 floats
    const int P1 = (S + 1) / 2;
    float*  R2  = R1 + P1 * 96;                // P2*80 floats

    const int t = threadIdx.x;
    const int b = blockIdx.x * TB + t;

    // ---- copy packed records into shared ----
    {
        const float4* s1 = (const float4*)g_rec1;
        float4* d1 = (float4*)R1;
        int n1 = P1 * 24;
        for (int i = t; i < n1; i += TB) d1[i] = s1[i];
        const float4* s2 = (const float4*)g_rec2;
        float4* d2 = (float4*)R2;
        for (int i = t; i < P2 * 20; i += TB) d2[i] = s2[i];
    }

    // ---- load E into shared (own column) + zero pad rows ----
    if (b < Btot) {
        const float4* xr = (const float4*)(x + (size_t)b * (MSZ * 4));
#pragma unroll
        for (int j = 0; j < MSZ; j++) {
            float4 v = xr[j];
            Esh[(2 * j) * TB + t]     = make_float2(v.x, v.y);
            Esh[(2 * j + 1) * TB + t] = make_float2(v.z, v.w);
        }
        Esh[82 * TB + t] = make_float2(0.f, 0.f);
        Esh[83 * TB + t] = make_float2(0.f, 0.f);
    }
    __syncthreads();
    if (b >= Btot) return;

    // ================= conv2 (k loop, packed over k-pairs) =================
    u64 Br0[HD], Bi0[HD], Br1[HD], Bi1[HD];
#pragma unroll
    for (int o = 0; o < HD; o++) { Br0[o] = Bi0[o] = Br1[o] = Bi1[o] = 0ULL; }

    for (int j = 0; j < P2; j++) {
        int k = 2 * j;
        float2 e0e = Esh[(2 * k) * TB + t];
        float2 e1e = Esh[(2 * k + 1) * TB + t];
        float2 e0o = Esh[(2 * k + 2) * TB + t];
        float2 e1o = Esh[(2 * k + 3) * TB + t];
        u64 e0r = pk(e0e.x, e0o.x), e0i = pk(e0e.y, e0o.y);
        u64 e1r = pk(e1e.x, e1o.x), e1i = pk(e1e.y, e1o.y);
        u64 n0i = ng(e0i), n1i = ng(e1i);
        const ulonglong2* w = (const ulonglong2*)(R2 + j * 80);
#pragma unroll
        for (int o = 0; o < HD; o++) {
            ulonglong2 wa = w[2 * o];       // {re pair, im pair} for i=0
            ulonglong2 wb = w[2 * o + 1];   // for i=1
            fma2(Br0[o], wa.x, e0r); fma2(Br0[o], wa.y, n0i);
            fma2(Br0[o], wb.x, e1r); fma2(Br0[o], wb.y, n1i);
            fma2(Bi0[o], wa.x, e0i); fma2(Bi0[o], wa.y, e0r);
            fma2(Bi0[o], wb.x, e1i); fma2(Bi0[o], wb.y, e1r);
            fma2(Br1[o], wa.x, e1r); fma2(Br1[o], wa.y, n1i);
            fma2(Br1[o], wb.x, e0r); fma2(Br1[o], wb.y, n0i);
            fma2(Bi1[o], wa.x, e1i); fma2(Bi1[o], wa.y, e1r);
            fma2(Bi1[o], wb.x, e0i); fma2(Bi1[o], wb.y, e0r);
        }
    }
    // reduce conv2 accumulators to scalars
    float br0[HD], bi0[HD], br1[HD], bi1[HD];
#pragma unroll
    for (int o = 0; o < HD; o++) {
        float2 v;
        v = upk(Br0[o]); br0[o] = v.x + v.y;
        v = upk(Bi0[o]); bi0[o] = v.x + v.y;
        v = upk(Br1[o]); br1[o] = v.x + v.y;
        v = upk(Bi1[o]); bi1[o] = v.x + v.y;
    }

    // ================= conv1 + pbc (s loop, packed over s-pairs) ===========
    u64 Ar0[HD], Ai0[HD], Ar1[HD], Ai1[HD];
#pragma unroll
    for (int o = 0; o < HD; o++) { Ar0[o] = Ai0[o] = Ar1[o] = Ai1[o] = 0ULL; }
    u64 pr0P = 0, pi0P = 0, pr1P = 0, pi1P = 0;

    for (int j = 0; j < P1; j++) {
        const float4* h = (const float4*)(R1 + j * 96);
        float4 he = h[0];
        float4 hoA = h[1];
        float4 hc = h[2];

        // even-s feature
        float F0r_e, F0i_e, F1r_e, F1i_e;
        {
            int k1 = __float_as_int(he.x), k2 = __float_as_int(he.y), k3 = __float_as_int(he.z);
            float2 a0 = Esh[k1 * TB + t], a1 = Esh[(k1 + 1) * TB + t];
            float2 q0 = Esh[k2 * TB + t], q1 = Esh[(k2 + 1) * TB + t];
            float2 n0 = Esh[k3 * TB + t], n1 = Esh[(k3 + 1) * TB + t];
            float Asr = a0.x * q0.x + a0.y * q0.y + a1.x * q1.x + a1.y * q1.y;
            float Asi = a0.y * q0.x - a0.x * q0.y + a1.y * q1.x - a1.x * q1.y;
            F0r_e = Asr * n0.x - Asi * n0.y; F0i_e = Asr * n0.y + Asi * n0.x;
            F1r_e = Asr * n1.x - Asi * n1.y; F1i_e = Asr * n1.y + Asi * n1.x;
        }
        // odd-s feature
        float F0r_o, F0i_o, F1r_o, F1i_o;
        {
            int k1 = __float_as_int(hoA.x), k2 = __float_as_int(hoA.y), k3 = __float_as_int(hoA.z);
            float2 a0 = Esh[k1 * TB + t], a1 = Esh[(k1 + 1) * TB + t];
            float2 q0 = Esh[k2 * TB + t], q1 = Esh[(k2 + 1) * TB + t];
            float2 n0 = Esh[k3 * TB + t], n1 = Esh[(k3 + 1) * TB + t];
            float Asr = a0.x * q0.x + a0.y * q0.y + a1.x * q1.x + a1.y * q1.y;
            float Asi = a0.y * q0.x - a0.x * q0.y + a1.y * q1.x - a1.x * q1.y;
            F0r_o = Asr * n0.x - Asi * n0.y; F0i_o = Asr * n0.y + Asi * n0.x;
            F1r_o = Asr * n1.x - Asi * n1.y; F1i_o = Asr * n1.y + Asi * n1.x;
        }

        u64 F0r = pk(F0r_e, F0r_o), F0i = pk(F0i_e, F0i_o);
        u64 F1r = pk(F1r_e, F1r_o), F1i = pk(F1i_e, F1i_o);
        u64 nF0i = ng(F0i), nF1i = ng(F1i);

        // pbc dot
        u64 Cre = pk(hc.x, hc.y), Cim = pk(hc.z, hc.w);
        u64 nCim = ng(Cim);
        fma2(pr0P, F0r, Cre); fma2(pr0P, F0i, nCim);
        fma2(pi0P, F0r, Cim); fma2(pi0P, F0i, Cre);
        fma2(pr1P, F1r, Cre); fma2(pr1P, F1i, nCim);
        fma2(pi1P, F1r, Cim); fma2(pi1P, F1i, Cre);

        const ulonglong2* w = (const ulonglong2*)(R1 + j * 96 + 16);
#pragma unroll
        for (int o = 0; o < HD; o++) {
            ulonglong2 wa = w[2 * o];
            ulonglong2 wb = w[2 * o + 1];
            fma2(Ar0[o], wa.x, F0r); fma2(Ar0[o], wa.y, nF0i);
            fma2(Ar0[o], wb.x, F1r); fma2(Ar0[o], wb.y, nF1i);
            fma2(Ai0[o], wa.x, F0i); fma2(Ai0[o], wa.y, F0r);
            fma2(Ai0[o], wb.x, F1i); fma2(Ai0[o], wb.y, F1r);
            fma2(Ar1[o], wa.x, F1r); fma2(Ar1[o], wa.y, nF1i);
            fma2(Ar1[o], wb.x, F0r); fma2(Ar1[o], wb.y, nF0i);
            fma2(Ai1[o], wa.x, F1i); fma2(Ai1[o], wa.y, F1r);
            fma2(Ai1[o], wb.x, F0i); fma2(Ai1[o], wb.y, F0r);
        }
    }

    // ================= epilogue =================
    float2 v;
    v = upk(pr0P); float pr0 = v.x + v.y;
    v = upk(pi0P); float pi0 = v.x + v.y;
    v = upk(pr1P); float pr1 = v.x + v.y;
    v = upk(pi1P); float pi1 = v.x + v.y;

    float tsk = task[(size_t)b * 4];
    float P = exp10f(tsk * 0.1f) * 0.5f;
    const float scl = 3.16227766016837939e-05f;  // 1e-4 / sqrt(10)
    float sc = scl * P * P;
    const int crow = 2 * (MSZ / 2);
    float2 Ec0 = Esh[crow * TB + t];
    float2 Ec1 = Esh[(crow + 1) * TB + t];

    float tr0 = 0.f, ti0 = 0.f, tr1 = 0.f, ti1 = 0.f;
#pragma unroll
    for (int o = 0; o < HD; o++) {
        float b1r = b1g[2 * o], b1i = b1g[2 * o + 1];
        float b2r = b2g[2 * o], b2i = b2g[2 * o + 1];
        float2 va;
        va = upk(Ar0[o]); float ar = va.x + va.y + b1r;
        va = upk(Ai0[o]); float ai = va.x + va.y + b1i;
        float brv = br0[o] + b2r, biv = bi0[o] + b2i;
        float rr = 2.f * (ar * brv + ai * biv);
        tr0 += rr * brv; ti0 += rr * biv;

        va = upk(Ar1[o]); ar = va.x + va.y + b1r;
        va = upk(Ai1[o]); ai = va.x + va.y + b1i;
        brv = br1[o] + b2r; biv = bi1[o] + b2i;
        rr = 2.f * (ar * brv + ai * biv);
        tr1 += rr * brv; ti1 += rr * biv;
    }

    float4 res;
    res.x = Ec0.x + P * pr0 + sc * tr0;
    res.y = Ec0.y + P * pi0 + sc * ti0;
    res.z = Ec1.x + P * pr1 + sc * tr1;
    res.w = Ec1.y + P * pi1 + sc * ti1;
    *(float4*)(out + (size_t)b * 4) = res;
}

extern "C" void kernel_launch(void* const* d_in, const int* in_sizes, int n_in,
                              void* d_out, int out_size) {
    const float* x     = (const float*)d_in[0];
    const float* task  = (const float*)d_in[1];
    const float* pbc_C = (const float*)d_in[2];
    const float* W1    = (const float*)d_in[3];
    const float* b1    = (const float*)d_in[4];
    const float* W2    = (const float*)d_in[5];
    const float* b2    = (const float*)d_in[6];
    const int*   m_idx = (const int*)d_in[7];
    const int*   n_idx = (const int*)d_in[8];
    int S = in_sizes[7];
    if (S > 2 * MAXP) S = 2 * MAXP;
    int B = out_size / 4;
    int P1 = (S + 1) / 2;

    size_t smem = (size_t)(84 * TB) * sizeof(float2)   // E (incl. 2 pad rows)
                + (size_t)(P1 * 96) * sizeof(float)    // rec1
                + (size_t)(P2 * 80) * sizeof(float);   // rec2
    cudaFuncSetAttribute(eqsonn_kernel,
                         cudaFuncAttributeMaxDynamicSharedMemorySize, (int)smem);

    prep_kernel<<<2, 128>>>(pbc_C, W1, W2, m_idx, n_idx, S);

    int blocks = (B + TB - 1) / TB;
    eqsonn_kernel<<<blocks, TB, smem>>>(x, task, b1, b2, (float*)d_out, S, B);
}

// round 3
// speedup vs baseline: 3.1454x; 1.1658x over previous
#include <cuda_runtime.h>

#define TB   256        // threads per block (2 halves)
#define HB   128        // batch elements per block
#define HD   10         // HDIM
#define MSZ  41         // M
#define MAXP 256        // max s-pairs (S<=512)
#define P2   21         // k-pairs for conv2 (ceil(41/2))

typedef unsigned long long u64;

// rec1: per s-pair j (s=2j,2j+1), 96 floats:
//  [0..2] byte-offsets (k1,k2,k3)*2048 for even s, [3] pad
//  [4..6] same for odd s, [7] pad
//  [8,9]=C.re(e,o) [10,11]=C.im(e,o) [12..15] pad
//  [16 + o*8 + i*4 + {0,1}] = W1[o][i].re (e,o); {2,3} = W1[o][i].im (e,o)
__device__ float g_rec1[MAXP * 96];
// rec2: per k-pair j, 80 floats: [o*8 + i*4 + {0,1}] = W2[o][i].re (e,o); {2,3}=im
__device__ float g_rec2[P2 * 80];

__device__ __forceinline__ u64 pk(float lo, float hi) {
    u64 r; asm("mov.b64 %0,{%1,%2};" : "=l"(r) : "f"(lo), "f"(hi)); return r;
}
__device__ __forceinline__ float2 upk(u64 v) {
    float2 f; asm("mov.b64 {%0,%1},%2;" : "=f"(f.x), "=f"(f.y) : "l"(v)); return f;
}
__device__ __forceinline__ void fma2(u64 &a, u64 x, u64 y) {
    asm("fma.rn.f32x2 %0,%1,%2,%0;" : "+l"(a) : "l"(x), "l"(y));
}
__device__ __forceinline__ u64 ng(u64 v) { return v ^ 0x8000000080000000ULL; }

__global__ void prep_kernel(const float* __restrict__ pbc_C,
                            const float* __restrict__ W1,
                            const float* __restrict__ W2,
                            const int*   __restrict__ m_idx,
                            const int*   __restrict__ n_idx,
                            int S) {
    int j = blockIdx.x * blockDim.x + threadIdx.x;
    int P1 = (S + 1) / 2;
    const int c = MSZ / 2;
    if (j < P1) {
        float* r = g_rec1 + j * 96;
        r[3] = 0.f; r[7] = 0.f;
        r[12] = r[13] = r[14] = r[15] = 0.f;
#pragma unroll
        for (int h = 0; h < 2; h++) {
            int s = 2 * j + h;
            bool v = (s < S);
            int m = v ? m_idx[s] : 0;
            int n = v ? n_idx[s] : 0;
            r[4 * h + 0] = __int_as_float(v ? (c + m) * 2048 : 0);
            r[4 * h + 1] = __int_as_float(v ? (c + m + n) * 2048 : 0);
            r[4 * h + 2] = __int_as_float(v ? (c + n) * 2048 : 0);
            r[8 + h]  = v ? pbc_C[2 * s + 0] : 0.f;
            r[10 + h] = v ? pbc_C[2 * s + 1] : 0.f;
#pragma unroll
            for (int oi = 0; oi < 2 * HD; oi++) {
                int base = 16 + oi * 4;
                r[base + h]     = v ? W1[(oi * S + s) * 2 + 0] : 0.f;
                r[base + 2 + h] = v ? W1[(oi * S + s) * 2 + 1] : 0.f;
            }
        }
    }
    if (j < P2) {
        float* r = g_rec2 + j * 80;
#pragma unroll
        for (int h = 0; h < 2; h++) {
            int k = 2 * j + h;
            bool v = (k < MSZ);
#pragma unroll
            for (int oi = 0; oi < 2 * HD; oi++) {
                int base = oi * 4;
                r[base + h]     = v ? W2[(oi * MSZ + k) * 2 + 0] : 0.f;
                r[base + 2 + h] = v ? W2[(oi * MSZ + k) * 2 + 1] : 0.f;
            }
        }
    }
}

__global__ __launch_bounds__(TB) void eqsonn_kernel(
    const float* __restrict__ x,
    const float* __restrict__ task,
    const float* __restrict__ b1g,
    const float* __restrict__ b2g,
    float* __restrict__ out,
    int S, int Btot) {
    extern __shared__ float sm[];
    // E4[k][tl]: float4 = (pol0.re, pol0.im, pol1.re, pol1.im); rows 0..40 + pad 41
    float4* E4 = (float4*)sm;                  // 42*HB float4
    float*  R1 = sm + 42 * HB * 4;             // P1*96 floats
    const int P1 = (S + 1) / 2;
    float*  R2 = R1 + P1 * 96;                 // P2*80 floats

    const int t    = threadIdx.x;
    const int half = t >> 7;
    const int tl   = t & (HB - 1);
    const int b    = blockIdx.x * HB + tl;

    // ---- copy packed records into shared (all threads) ----
    {
        const float4* s1 = (const float4*)g_rec1;
        float4* d1 = (float4*)R1;
        int n1 = P1 * 24;
        for (int i = t; i < n1; i += TB) d1[i] = s1[i];
        const float4* s2 = (const float4*)g_rec2;
        float4* d2 = (float4*)R2;
        for (int i = t; i < P2 * 20; i += TB) d2[i] = s2[i];
    }

    // ---- load E rows (split across halves), zero pad row ----
    if (b < Btot) {
        const float4* xr = (const float4*)(x + (size_t)b * (MSZ * 4));
        int j0 = half * 21, j1 = half ? MSZ : 21;
        for (int j = j0; j < j1; j++)
            E4[j * HB + tl] = xr[j];
        if (half) E4[41 * HB + tl] = make_float4(0.f, 0.f, 0.f, 0.f);
    }
    __syncthreads();

    const char* Eb = (const char*)E4 + tl * 16;
#define E4AT(off) (*(const float4*)(Eb + (off)))

    // ================= conv2 (k-pairs, split across halves) =================
    u64 Br0[HD], Bi0[HD], Br1[HD], Bi1[HD];
#pragma unroll
    for (int o = 0; o < HD; o++) { Br0[o] = Bi0[o] = Br1[o] = Bi1[o] = 0ULL; }
    {
        int j0 = half * 11, j1 = half ? P2 : 11;
        for (int j = j0; j < j1; j++) {
            float4 ve = E4AT(j * 4096);
            float4 vo = E4AT(j * 4096 + 2048);
            u64 e0r = pk(ve.x, vo.x), e0i = pk(ve.y, vo.y);
            u64 e1r = pk(ve.z, vo.z), e1i = pk(ve.w, vo.w);
            u64 n0i = ng(e0i), n1i = ng(e1i);
            const ulonglong2* w = (const ulonglong2*)(R2 + j * 80);
#pragma unroll
            for (int o = 0; o < HD; o++) {
                ulonglong2 wa = w[2 * o];
                ulonglong2 wb = w[2 * o + 1];
                fma2(Br0[o], wa.x, e0r); fma2(Br0[o], wa.y, n0i);
                fma2(Br0[o], wb.x, e1r); fma2(Br0[o], wb.y, n1i);
                fma2(Bi0[o], wa.x, e0i); fma2(Bi0[o], wa.y, e0r);
                fma2(Bi0[o], wb.x, e1i); fma2(Bi0[o], wb.y, e1r);
                fma2(Br1[o], wa.x, e1r); fma2(Br1[o], wa.y, n1i);
                fma2(Br1[o], wb.x, e0r); fma2(Br1[o], wb.y, n0i);
                fma2(Bi1[o], wa.x, e1i); fma2(Bi1[o], wa.y, e1r);
                fma2(Bi1[o], wb.x, e0i); fma2(Bi1[o], wb.y, e0r);
            }
        }
    }
    float br0[HD], bi0[HD], br1[HD], bi1[HD];
#pragma unroll
    for (int o = 0; o < HD; o++) {
        float2 v;
        v = upk(Br0[o]); br0[o] = v.x + v.y;
        v = upk(Bi0[o]); bi0[o] = v.x + v.y;
        v = upk(Br1[o]); br1[o] = v.x + v.y;
        v = upk(Bi1[o]); bi1[o] = v.x + v.y;
    }

    // ================= conv1 + pbc (s-pairs, split across halves) ===========
    u64 Ar0[HD], Ai0[HD], Ar1[HD], Ai1[HD];
#pragma unroll
    for (int o = 0; o < HD; o++) { Ar0[o] = Ai0[o] = Ar1[o] = Ai1[o] = 0ULL; }
    u64 pr0P = 0, pi0P = 0, pr1P = 0, pi1P = 0;
    {
        int split = (P1 + 1) / 2;
        int j0 = half * split;
        int j1 = half ? P1 : split;
        for (int j = j0; j < j1; j++) {
            const float4* h = (const float4*)(R1 + j * 96);
            float4 he = h[0];
            float4 ho = h[1];
            float4 hc = h[2];

            float F0r_e, F0i_e, F1r_e, F1i_e;
            {
                float4 a = E4AT(__float_as_int(he.x));
                float4 q = E4AT(__float_as_int(he.y));
                float4 n = E4AT(__float_as_int(he.z));
                float Asr = a.x * q.x + a.y * q.y + a.z * q.z + a.w * q.w;
                float Asi = a.y * q.x - a.x * q.y + a.w * q.z - a.z * q.w;
                F0r_e = Asr * n.x - Asi * n.y; F0i_e = Asr * n.y + Asi * n.x;
                F1r_e = Asr * n.z - Asi * n.w; F1i_e = Asr * n.w + Asi * n.z;
            }
            float F0r_o, F0i_o, F1r_o, F1i_o;
            {
                float4 a = E4AT(__float_as_int(ho.x));
                float4 q = E4AT(__float_as_int(ho.y));
                float4 n = E4AT(__float_as_int(ho.z));
                float Asr = a.x * q.x + a.y * q.y + a.z * q.z + a.w * q.w;
                float Asi = a.y * q.x - a.x * q.y + a.w * q.z - a.z * q.w;
                F0r_o = Asr * n.x - Asi * n.y; F0i_o = Asr * n.y + Asi * n.x;
                F1r_o = Asr * n.z - Asi * n.w; F1i_o = Asr * n.w + Asi * n.z;
            }

            u64 F0r = pk(F0r_e, F0r_o), F0i = pk(F0i_e, F0i_o);
            u64 F1r = pk(F1r_e, F1r_o), F1i = pk(F1i_e, F1i_o);
            u64 nF0i = ng(F0i), nF1i = ng(F1i);

            u64 Cre = pk(hc.x, hc.y), Cim = pk(hc.z, hc.w);
            u64 nCim = ng(Cim);
            fma2(pr0P, F0r, Cre); fma2(pr0P, F0i, nCim);
            fma2(pi0P, F0r, Cim); fma2(pi0P, F0i, Cre);
            fma2(pr1P, F1r, Cre); fma2(pr1P, F1i, nCim);
            fma2(pi1P, F1r, Cim); fma2(pi1P, F1i, Cre);

            const ulonglong2* w = (const ulonglong2*)(R1 + j * 96 + 16);
#pragma unroll
            for (int o = 0; o < HD; o++) {
                ulonglong2 wa = w[2 * o];
                ulonglong2 wb = w[2 * o + 1];
                fma2(Ar0[o], wa.x, F0r); fma2(Ar0[o], wa.y, nF0i);
                fma2(Ar0[o], wb.x, F1r); fma2(Ar0[o], wb.y, nF1i);
                fma2(Ai0[o], wa.x, F0i); fma2(Ai0[o], wa.y, F0r);
                fma2(Ai0[o], wb.x, F1i); fma2(Ai0[o], wb.y, F1r);
                fma2(Ar1[o], wa.x, F1r); fma2(Ar1[o], wa.y, nF1i);
                fma2(Ar1[o], wb.x, F0r); fma2(Ar1[o], wb.y, nF0i);
                fma2(Ai1[o], wa.x, F1i); fma2(Ai1[o], wa.y, F1r);
                fma2(Ai1[o], wb.x, F0i); fma2(Ai1[o], wb.y, F0r);
            }
        }
    }

    // ---- pack own partials into 84 floats ----
    float my[84];
    {
        float2 v;
        v = upk(pr0P); my[0] = v.x + v.y;
        v = upk(pi0P); my[1] = v.x + v.y;
        v = upk(pr1P); my[2] = v.x + v.y;
        v = upk(pi1P); my[3] = v.x + v.y;
#pragma unroll
        for (int o = 0; o < HD; o++) {
            v = upk(Ar0[o]); my[4 + 4 * o + 0] = v.x + v.y;
            v = upk(Ai0[o]); my[4 + 4 * o + 1] = v.x + v.y;
            v = upk(Ar1[o]); my[4 + 4 * o + 2] = v.x + v.y;
            v = upk(Ai1[o]); my[4 + 4 * o + 3] = v.x + v.y;
        }
#pragma unroll
        for (int o = 0; o < HD; o++) {
            my[44 + 4 * o + 0] = br0[o];
            my[44 + 4 * o + 1] = bi0[o];
            my[44 + 4 * o + 2] = br1[o];
            my[44 + 4 * o + 3] = bi1[o];
        }
    }

    // ---- cross-half reduction through smem (reuse R1 region) ----
    __syncthreads();                       // everyone done reading R1
    float* red = R1;
    if (half) {
#pragma unroll
        for (int i = 0; i < 84; i++) red[tl * 85 + i] = my[i];
    }
    __syncthreads();
    if (half) return;

#pragma unroll
    for (int i = 0; i < 84; i++) my[i] += red[tl * 85 + i];

    // ================= epilogue (half 0 only) =================
    if (b >= Btot) return;
    float tsk = task[(size_t)b * 4];
    float P = exp10f(tsk * 0.1f) * 0.5f;
    const float scl = 3.16227766016837939e-05f;  // 1e-4 / sqrt(10)
    float sc = scl * P * P;
    float4 Ec = E4AT(20 * 2048);

    float tr0 = 0.f, ti0 = 0.f, tr1 = 0.f, ti1 = 0.f;
#pragma unroll
    for (int o = 0; o < HD; o++) {
        float b1r = b1g[2 * o], b1i = b1g[2 * o + 1];
        float b2r = b2g[2 * o], b2i = b2g[2 * o + 1];
        float ar = my[4 + 4 * o + 0] + b1r;
        float ai = my[4 + 4 * o + 1] + b1i;
        float brv = my[44 + 4 * o + 0] + b2r;
        float biv = my[44 + 4 * o + 1] + b2i;
        float rr = 2.f * (ar * brv + ai * biv);
        tr0 += rr * brv; ti0 += rr * biv;

        ar = my[4 + 4 * o + 2] + b1r;
        ai = my[4 + 4 * o + 3] + b1i;
        brv = my[44 + 4 * o + 2] + b2r;
        biv = my[44 + 4 * o + 3] + b2i;
        rr = 2.f * (ar * brv + ai * biv);
        tr1 += rr * brv; ti1 += rr * biv;
    }

    float4 res;
    res.x = Ec.x + P * my[0] + sc * tr0;
    res.y = Ec.y + P * my[1] + sc * ti0;
    res.z = Ec.z + P * my[2] + sc * tr1;
    res.w = Ec.w + P * my[3] + sc * ti1;
    *(float4*)(out + (size_t)b * 4) = res;
}

extern "C" void kernel_launch(void* const* d_in, const int* in_sizes, int n_in,
                              void* d_out, int out_size) {
    const float* x     = (const float*)d_in[0];
    const float* task  = (const float*)d_in[1];
    const float* pbc_C = (const float*)d_in[2];
    const float* W1    = (const float*)d_in[3];
    const float* b1    = (const float*)d_in[4];
    const float* W2    = (const float*)d_in[5];
    const float* b2    = (const float*)d_in[6];
    const int*   m_idx = (const int*)d_in[7];
    const int*   n_idx = (const int*)d_in[8];
    int S = in_sizes[7];
    if (S > 2 * MAXP) S = 2 * MAXP;
    int B = out_size / 4;
    int P1 = (S + 1) / 2;

    size_t smem = (size_t)(42 * HB) * sizeof(float4)   // E (incl. pad row)
                + (size_t)(P1 * 96) * sizeof(float)    // rec1
                + (size_t)(P2 * 80) * sizeof(float);   // rec2
    cudaFuncSetAttribute(eqsonn_kernel,
                         cudaFuncAttributeMaxDynamicSharedMemorySize, (int)smem);

    prep_kernel<<<2, 128>>>(pbc_C, W1, W2, m_idx, n_idx, S);

    int blocks = (B + HB - 1) / HB;
    eqsonn_kernel<<<blocks, TB, smem>>>(x, task, b1, b2, (float*)d_out, S, B);
}

// round 4
// speedup vs baseline: 4.1728x; 1.3267x over previous
#include <cuda_runtime.h>

#define TB   256        // threads per block (2 halves)
#define HB   128        // batch elements per block
#define HD   10         // HDIM
#define MSZ  41         // M
#define MAXP 256        // max s-pairs (S<=512)
#define P2   21         // k-pairs for conv2 (ceil(41/2))

typedef unsigned long long u64;

// rec1: per s-pair j (s=2j,2j+1), 96 floats:
//  [0..2] byte-offsets (k1,k2,k3)*2048 for even s, [3] pad
//  [4..6] same for odd s, [7] pad
//  [8,9]=C.re/2 (e,o) [10,11]=C.im/2 (e,o) [12..15] pad
//  weights at [16 + o*8]: Ws.re(e,o), Ws.im(e,o), Wd.re(e,o), Wd.im(e,o)
//  where Ws=(W1[o][0]+W1[o][1])/2, Wd=(W1[o][0]-W1[o][1])/2
__device__ float g_rec1[MAXP * 96];
// rec2: per k-pair j, 80 floats: [o*8]: Ws2.re(e,o), Ws2.im(e,o), Wd2.re(e,o), Wd2.im(e,o)
__device__ float g_rec2[P2 * 80];

__device__ __forceinline__ u64 pk(float lo, float hi) {
    u64 r; asm("mov.b64 %0,{%1,%2};" : "=l"(r) : "f"(lo), "f"(hi)); return r;
}
__device__ __forceinline__ float2 upk(u64 v) {
    float2 f; asm("mov.b64 {%0,%1},%2;" : "=f"(f.x), "=f"(f.y) : "l"(v)); return f;
}
__device__ __forceinline__ void fma2(u64 &a, u64 x, u64 y) {
    asm("fma.rn.f32x2 %0,%1,%2,%0;" : "+l"(a) : "l"(x), "l"(y));
}
__device__ __forceinline__ u64 mul2(u64 x, u64 y) {
    u64 r; asm("mul.rn.f32x2 %0,%1,%2;" : "=l"(r) : "l"(x), "l"(y)); return r;
}
__device__ __forceinline__ u64 ng(u64 v) { return v ^ 0x8000000080000000ULL; }

__global__ void prep_kernel(const float* __restrict__ pbc_C,
                            const float* __restrict__ W1,
                            const float* __restrict__ W2,
                            const int*   __restrict__ m_idx,
                            const int*   __restrict__ n_idx,
                            int S) {
    int j = blockIdx.x * blockDim.x + threadIdx.x;
    int P1 = (S + 1) / 2;
    const int c = MSZ / 2;
    if (j < P1) {
        float* r = g_rec1 + j * 96;
        r[3] = 0.f; r[7] = 0.f;
        r[12] = r[13] = r[14] = r[15] = 0.f;
#pragma unroll
        for (int h = 0; h < 2; h++) {
            int s = 2 * j + h;
            bool v = (s < S);
            int m = v ? m_idx[s] : 0;
            int n = v ? n_idx[s] : 0;
            r[4 * h + 0] = __int_as_float(v ? (c + m) * 2048 : 0);
            r[4 * h + 1] = __int_as_float(v ? (c + m + n) * 2048 : 0);
            r[4 * h + 2] = __int_as_float(v ? (c + n) * 2048 : 0);
            r[8 + h]  = v ? 0.5f * pbc_C[2 * s + 0] : 0.f;
            r[10 + h] = v ? 0.5f * pbc_C[2 * s + 1] : 0.f;
#pragma unroll
            for (int o = 0; o < HD; o++) {
                float war = v ? W1[((2 * o) * S + s) * 2 + 0] : 0.f;
                float wai = v ? W1[((2 * o) * S + s) * 2 + 1] : 0.f;
                float wbr = v ? W1[((2 * o + 1) * S + s) * 2 + 0] : 0.f;
                float wbi = v ? W1[((2 * o + 1) * S + s) * 2 + 1] : 0.f;
                int base = 16 + o * 8;
                r[base + 0 + h] = 0.5f * (war + wbr);
                r[base + 2 + h] = 0.5f * (wai + wbi);
                r[base + 4 + h] = 0.5f * (war - wbr);
                r[base + 6 + h] = 0.5f * (wai - wbi);
            }
        }
    }
    if (j < P2) {
        float* r = g_rec2 + j * 80;
#pragma unroll
        for (int h = 0; h < 2; h++) {
            int k = 2 * j + h;
            bool v = (k < MSZ);
#pragma unroll
            for (int o = 0; o < HD; o++) {
                float war = v ? W2[((2 * o) * MSZ + k) * 2 + 0] : 0.f;
                float wai = v ? W2[((2 * o) * MSZ + k) * 2 + 1] : 0.f;
                float wbr = v ? W2[((2 * o + 1) * MSZ + k) * 2 + 0] : 0.f;
                float wbi = v ? W2[((2 * o + 1) * MSZ + k) * 2 + 1] : 0.f;
                int base = o * 8;
                r[base + 0 + h] = 0.5f * (war + wbr);
                r[base + 2 + h] = 0.5f * (wai + wbi);
                r[base + 4 + h] = 0.5f * (war - wbr);
                r[base + 6 + h] = 0.5f * (wai - wbi);
            }
        }
    }
}

__global__ __launch_bounds__(TB) void eqsonn_kernel(
    const float* __restrict__ x,
    const float* __restrict__ task,
    const float* __restrict__ b1g,
    const float* __restrict__ b2g,
    float* __restrict__ out,
    int S, int Btot) {
    extern __shared__ float sm[];
    float4* E4 = (float4*)sm;                  // 42*HB float4 (row 41 = zero pad)
    float*  R1 = sm + 42 * HB * 4;             // P1*96 floats
    const int P1 = (S + 1) / 2;
    float*  R2 = R1 + P1 * 96;                 // P2*80 floats

    const int t    = threadIdx.x;
    const int half = t >> 7;
    const int tl   = t & (HB - 1);
    const int b    = blockIdx.x * HB + tl;

    // ---- copy packed records into shared ----
    {
        const float4* s1 = (const float4*)g_rec1;
        float4* d1 = (float4*)R1;
        int n1 = P1 * 24;
        for (int i = t; i < n1; i += TB) d1[i] = s1[i];
        const float4* s2 = (const float4*)g_rec2;
        float4* d2 = (float4*)R2;
        for (int i = t; i < P2 * 20; i += TB) d2[i] = s2[i];
    }

    // ---- load E rows (split across halves), zero pad row ----
    if (b < Btot) {
        const float4* xr = (const float4*)(x + (size_t)b * (MSZ * 4));
        int j0 = half * 21, j1 = half ? MSZ : 21;
        for (int j = j0; j < j1; j++)
            E4[j * HB + tl] = xr[j];
        if (half) E4[41 * HB + tl] = make_float4(0.f, 0.f, 0.f, 0.f);
    }
    __syncthreads();

    const char* Eb = (const char*)E4 + tl * 16;
#define E4AT(off) (*(const float4*)(Eb + (off)))

    // ================= conv2 (k-pairs, sum/diff basis) =================
    u64 Bsr[HD], Bsi[HD], Bdr[HD], Bdi[HD];
#pragma unroll
    for (int o = 0; o < HD; o++) { Bsr[o] = Bsi[o] = Bdr[o] = Bdi[o] = 0ULL; }
    {
        int j0 = half * 11, j1 = half ? P2 : 11;
        for (int j = j0; j < j1; j++) {
            float4 ve = E4AT(j * 4096);
            float4 vo = E4AT(j * 4096 + 2048);
            u64 esr = pk(ve.x + ve.z, vo.x + vo.z);
            u64 esi = pk(ve.y + ve.w, vo.y + vo.w);
            u64 edr = pk(ve.x - ve.z, vo.x - vo.z);
            u64 edi = pk(ve.y - ve.w, vo.y - vo.w);
            u64 nesi = ng(esi), nedi = ng(edi);
            const ulonglong2* w = (const ulonglong2*)(R2 + j * 80);
#pragma unroll
            for (int o = 0; o < HD; o++) {
                ulonglong2 ws = w[2 * o];       // {Ws.re pair, Ws.im pair}
                ulonglong2 wd = w[2 * o + 1];   // {Wd.re pair, Wd.im pair}
                fma2(Bsr[o], ws.x, esr); fma2(Bsr[o], ws.y, nesi);
                fma2(Bsi[o], ws.x, esi); fma2(Bsi[o], ws.y, esr);
                fma2(Bdr[o], wd.x, edr); fma2(Bdr[o], wd.y, nedi);
                fma2(Bdi[o], wd.x, edi); fma2(Bdi[o], wd.y, edr);
            }
        }
    }
    float bs_r[HD], bs_i[HD], bd_r[HD], bd_i[HD];
#pragma unroll
    for (int o = 0; o < HD; o++) {
        float2 v;
        v = upk(Bsr[o]); bs_r[o] = v.x + v.y;
        v = upk(Bsi[o]); bs_i[o] = v.x + v.y;
        v = upk(Bdr[o]); bd_r[o] = v.x + v.y;
        v = upk(Bdi[o]); bd_i[o] = v.x + v.y;
    }

    // ================= conv1 + pbc (s-pairs, sum/diff basis) ===========
    u64 Asr[HD], Asi[HD], Adr[HD], Adi[HD];
#pragma unroll
    for (int o = 0; o < HD; o++) { Asr[o] = Asi[o] = Adr[o] = Adi[o] = 0ULL; }
    u64 psr = 0, psi = 0, pdr = 0, pdi = 0;
    {
        int split = (P1 + 1) / 2;
        int j0 = half * split;
        int j1 = half ? P1 : split;
        for (int j = j0; j < j1; j++) {
            const float4* h = (const float4*)(R1 + j * 96);
            float4 he = h[0];
            float4 ho = h[1];
            float4 hc = h[2];

            // even-s triplet scalar + pol sum/diff of E[c+n]
            float Ar_e, Ai_e, nsr_e, nsi_e, ndr_e, ndi_e;
            {
                float4 a = E4AT(__float_as_int(he.x));
                float4 q = E4AT(__float_as_int(he.y));
                float4 n = E4AT(__float_as_int(he.z));
                Ar_e = a.x * q.x + a.y * q.y + a.z * q.z + a.w * q.w;
                Ai_e = a.y * q.x - a.x * q.y + a.w * q.z - a.z * q.w;
                nsr_e = n.x + n.z; nsi_e = n.y + n.w;
                ndr_e = n.x - n.z; ndi_e = n.y - n.w;
            }
            float Ar_o, Ai_o, nsr_o, nsi_o, ndr_o, ndi_o;
            {
                float4 a = E4AT(__float_as_int(ho.x));
                float4 q = E4AT(__float_as_int(ho.y));
                float4 n = E4AT(__float_as_int(ho.z));
                Ar_o = a.x * q.x + a.y * q.y + a.z * q.z + a.w * q.w;
                Ai_o = a.y * q.x - a.x * q.y + a.w * q.z - a.z * q.w;
                nsr_o = n.x + n.z; nsi_o = n.y + n.w;
                ndr_o = n.x - n.z; ndi_o = n.y - n.w;
            }

            u64 TAr = pk(Ar_e, Ar_o), TAi = pk(Ai_e, Ai_o);
            u64 nTAi = ng(TAi);
            u64 ns_r = pk(nsr_e, nsr_o), ns_i = pk(nsi_e, nsi_o);
            u64 nd_r = pk(ndr_e, ndr_o), nd_i = pk(ndi_e, ndi_o);

            // Gs = As * (n0+n1), Gd = As * (n0-n1)   (complex, f32x2)
            u64 Gsr = mul2(TAr, ns_r); fma2(Gsr, nTAi, ns_i);
            u64 Gsi = mul2(TAr, ns_i); fma2(Gsi, TAi, ns_r);
            u64 Gdr = mul2(TAr, nd_r); fma2(Gdr, nTAi, nd_i);
            u64 Gdi = mul2(TAr, nd_i); fma2(Gdi, TAi, nd_r);
            u64 nGsi = ng(Gsi), nGdi = ng(Gdi);

            // pbc in sum/diff basis (C pre-halved)
            u64 Cre = pk(hc.x, hc.y), Cim = pk(hc.z, hc.w);
            u64 nCim = ng(Cim);
            fma2(psr, Gsr, Cre); fma2(psr, Gsi, nCim);
            fma2(psi, Gsr, Cim); fma2(psi, Gsi, Cre);
            fma2(pdr, Gdr, Cre); fma2(pdr, Gdi, nCim);
            fma2(pdi, Gdr, Cim); fma2(pdi, Gdi, Cre);

            const ulonglong2* w = (const ulonglong2*)(R1 + j * 96 + 16);
#pragma unroll
            for (int o = 0; o < HD; o++) {
                ulonglong2 ws = w[2 * o];
                ulonglong2 wd = w[2 * o + 1];
                fma2(Asr[o], ws.x, Gsr); fma2(Asr[o], ws.y, nGsi);
                fma2(Asi[o], ws.x, Gsi); fma2(Asi[o], ws.y, Gsr);
                fma2(Adr[o], wd.x, Gdr); fma2(Adr[o], wd.y, nGdi);
                fma2(Adi[o], wd.x, Gdi); fma2(Adi[o], wd.y, Gdr);
            }
        }
    }

    // ---- pack partials (convert back from sum/diff basis) ----
    float my[84];
    {
        float2 v;
        v = upk(psr); float ps_r = v.x + v.y;
        v = upk(psi); float ps_i = v.x + v.y;
        v = upk(pdr); float pd_r = v.x + v.y;
        v = upk(pdi); float pd_i = v.x + v.y;
        my[0] = ps_r + pd_r; my[1] = ps_i + pd_i;
        my[2] = ps_r - pd_r; my[3] = ps_i - pd_i;
#pragma unroll
        for (int o = 0; o < HD; o++) {
            v = upk(Asr[o]); float asr_ = v.x + v.y;
            v = upk(Asi[o]); float asi_ = v.x + v.y;
            v = upk(Adr[o]); float adr_ = v.x + v.y;
            v = upk(Adi[o]); float adi_ = v.x + v.y;
            my[4 + 4 * o + 0] = asr_ + adr_;
            my[4 + 4 * o + 1] = asi_ + adi_;
            my[4 + 4 * o + 2] = asr_ - adr_;
            my[4 + 4 * o + 3] = asi_ - adi_;
        }
#pragma unroll
        for (int o = 0; o < HD; o++) {
            my[44 + 4 * o + 0] = bs_r[o] + bd_r[o];
            my[44 + 4 * o + 1] = bs_i[o] + bd_i[o];
            my[44 + 4 * o + 2] = bs_r[o] - bd_r[o];
            my[44 + 4 * o + 3] = bs_i[o] - bd_i[o];
        }
    }

    // ---- cross-half reduction through smem (reuse R1 region) ----
    __syncthreads();
    float* red = R1;
    if (half) {
#pragma unroll
        for (int i = 0; i < 84; i++) red[tl * 85 + i] = my[i];
    }
    __syncthreads();
    if (half) return;

#pragma unroll
    for (int i = 0; i < 84; i++) my[i] += red[tl * 85 + i];

    // ================= epilogue (half 0 only) =================
    if (b >= Btot) return;
    float tsk = task[(size_t)b * 4];
    float P = exp10f(tsk * 0.1f) * 0.5f;
    const float scl = 3.16227766016837939e-05f;  // 1e-4 / sqrt(10)
    float sc = scl * P * P;
    float4 Ec = E4AT(20 * 2048);

    float tr0 = 0.f, ti0 = 0.f, tr1 = 0.f, ti1 = 0.f;
#pragma unroll
    for (int o = 0; o < HD; o++) {
        float b1r = b1g[2 * o], b1i = b1g[2 * o + 1];
        float b2r = b2g[2 * o], b2i = b2g[2 * o + 1];
        float ar = my[4 + 4 * o + 0] + b1r;
        float ai = my[4 + 4 * o + 1] + b1i;
        float brv = my[44 + 4 * o + 0] + b2r;
        float biv = my[44 + 4 * o + 1] + b2i;
        float rr = 2.f * (ar * brv + ai * biv);
        tr0 += rr * brv; ti0 += rr * biv;

        ar = my[4 + 4 * o + 2] + b1r;
        ai = my[4 + 4 * o + 3] + b1i;
        brv = my[44 + 4 * o + 2] + b2r;
        biv = my[44 + 4 * o + 3] + b2i;
        rr = 2.f * (ar * brv + ai * biv);
        tr1 += rr * brv; ti1 += rr * biv;
    }

    float4 res;
    res.x = Ec.x + P * my[0] + sc * tr0;
    res.y = Ec.y + P * my[1] + sc * ti0;
    res.z = Ec.z + P * my[2] + sc * tr1;
    res.w = Ec.w + P * my[3] + sc * ti1;
    *(float4*)(out + (size_t)b * 4) = res;
}

extern "C" void kernel_launch(void* const* d_in, const int* in_sizes, int n_in,
                              void* d_out, int out_size) {
    const float* x     = (const float*)d_in[0];
    const float* task  = (const float*)d_in[1];
    const float* pbc_C = (const float*)d_in[2];
    const float* W1    = (const float*)d_in[3];
    const float* b1    = (const float*)d_in[4];
    const float* W2    = (const float*)d_in[5];
    const float* b2    = (const float*)d_in[6];
    const int*   m_idx = (const int*)d_in[7];
    const int*   n_idx = (const int*)d_in[8];
    int S = in_sizes[7];
    if (S > 2 * MAXP) S = 2 * MAXP;
    int B = out_size / 4;
    int P1 = (S + 1) / 2;

    size_t smem = (size_t)(42 * HB) * sizeof(float4)
                + (size_t)(P1 * 96) * sizeof(float)
                + (size_t)(P2 * 80) * sizeof(float);
    cudaFuncSetAttribute(eqsonn_kernel,
                         cudaFuncAttributeMaxDynamicSharedMemorySize, (int)smem);

    prep_kernel<<<2, 128>>>(pbc_C, W1, W2, m_idx, n_idx, S);

    int blocks = (B + HB - 1) / HB;
    eqsonn_kernel<<<blocks, TB, smem>>>(x, task, b1, b2, (float*)d_out, S, B);
}